// round 13
// baseline (speedup 1.0000x reference)
#include <cuda_runtime.h>
#include <cuda_fp16.h>
#include <cstdint>
#include <cstddef>

#define MDIM 16
#define KDIM 8192
#define NDIM 8192
#define KSPLIT 16
#define KPER 512               // k per split
#define NGRP 4                 // 128-k groups per split
#define NT 16                  // n tiles (512 n each)
#define THREADS 512
#define N8W 4                  // n8 blocks per warp (16 warps x 4 = 64 per CTA)
#define GEMM_CTAS (NT * KSPLIT)        // 256
#define TOTAL_CTAS (GEMM_CTAS + NT)    // + 16 tail-combine CTAs

// smem: raw x [16][516] floats, then frags [32 blocks][32 lanes] uint4
#define RAW_ROW 516
#define SM_FRAG_OFF 33024      // 16*516*4, 16B aligned
#define SM_TOTAL (33024 + 32 * 32 * 16)   // 49408 B -> 2 CTAs/SM

__device__ __align__(16) float g_partial[KSPLIT][1024][128];   // 8 MB
__device__ int g_cnt[NT];      // per-tile arrival counters (self-resetting)

__device__ __forceinline__ void mma16816(float4& c,
                                         uint32_t a0, uint32_t a1, uint32_t a2, uint32_t a3,
                                         uint32_t b0, uint32_t b1) {
    asm volatile(
        "mma.sync.aligned.m16n8k16.row.col.f32.f16.f16.f32 "
        "{%0,%1,%2,%3},{%4,%5,%6,%7},{%8,%9},{%0,%1,%2,%3};"
        : "+f"(c.x), "+f"(c.y), "+f"(c.z), "+f"(c.w)
        : "r"(a0), "r"(a1), "r"(a2), "r"(a3), "r"(b0), "r"(b1));
}

// one int32 (8 nibbles) -> half2 {q[c], q[c+4]} * s + z  (bias removed exactly)
__device__ __forceinline__ uint32_t dq2(uint32_t w, uint32_t c4, __half2 s2, __half2 z2) {
    uint32_t t = ((w >> c4) & 0x000F000Fu) | 0x64006400u;
    uint32_t bu = 0x64006400u;
    __half2 q = __hsub2(*reinterpret_cast<__half2*>(&t), *reinterpret_cast<__half2*>(&bu));
    __half2 r = __hfma2(q, s2, z2);
    return *reinterpret_cast<uint32_t*>(&r);
}

__global__ void __launch_bounds__(THREADS, 2) wq_gemm(
    const float* __restrict__ x, const int* __restrict__ qw,
    const float* __restrict__ scales, const float* __restrict__ zeros,
    const float* __restrict__ bias, float* __restrict__ out) {
    extern __shared__ char smem[];
    const int tid = threadIdx.x;
    const int bid = blockIdx.x;

    if (bid >= GEMM_CTAS) {
        // -------- tail-combine CTA (scheduled last; gemm never waits on us) --------
        const int j = bid - GEMM_CTAS;          // tile 0..15
        if (tid == 0) {
            int v;
            do {
                asm volatile("ld.acquire.gpu.b32 %0, [%1];" : "=r"(v) : "l"(&g_cnt[j]));
                if (v < KSPLIT) __nanosleep(128);
            } while (v < KSPLIT);
        }
        __syncthreads();
        // tile j outputs: nb in [j*64, j*64+64), off 0..127 -> 8192 outputs, 16/thread
#pragma unroll
        for (int u = 0; u < 16; u++) {
            int t = u * THREADS + tid;          // 0..8191
            int nbl = t >> 7, o = t & 127;
            int nb = j * 64 + nbl;
            float s = 0.f;
#pragma unroll
            for (int k2 = 0; k2 < KSPLIT; k2++) s += g_partial[k2][nb][o];
            int m = o >> 3, n = nb * 8 + (o & 7);
            out[(size_t)m * NDIM + n] = s + bias[n];
        }
        __syncthreads();
        if (tid == 0) atomicExch(&g_cnt[j], 0);   // reset for next graph replay
        return;
    }

    // ---------------- gemm CTA ----------------
    float* xraw = reinterpret_cast<float*>(smem);
    uint4* frag = reinterpret_cast<uint4*>(smem + SM_FRAG_OFF);
    const int nt = bid & (NT - 1);
    const int ks = bid >> 4;

    // phase 1: coalesced raw x chunk [16][512] -> smem (padded rows)
    const float* xg = x + ks * KPER;
#pragma unroll
    for (int i = 0; i < 4; i++) {
        int e = tid + i * THREADS;          // 0..2047 float4 slots
        int r = e >> 7;                     // 128 float4 per row
        int kk = (e & 127) << 2;
        float4 v = *reinterpret_cast<const float4*>(xg + (size_t)r * KDIM + kk);
        *reinterpret_cast<float4*>(xraw + r * RAW_ROW + kk) = v;
    }
    __syncthreads();

    // phase 2: pack A-fragments (virtual-k permutation: 2c<->c, 2c+1<->c+4)
#pragma unroll
    for (int j = 0; j < 2; j++) {
        int e = tid + j * THREADS;          // 0..1023 = (block, lane)
        int b = e >> 5, l = e & 31;
        int r = l >> 2, c = l & 3, kb = b * 16;
        const float* r0 = xraw + r * RAW_ROW + kb;
        const float* r1 = xraw + (r + 8) * RAW_ROW + kb;
        __half2 a0 = __floats2half2_rn(r0[c], r0[c + 4]);
        __half2 a1 = __floats2half2_rn(r1[c], r1[c + 4]);
        __half2 a2 = __floats2half2_rn(r0[8 + c], r0[12 + c]);
        __half2 a3 = __floats2half2_rn(r1[8 + c], r1[12 + c]);
        uint4 f;
        f.x = *reinterpret_cast<uint32_t*>(&a0);
        f.y = *reinterpret_cast<uint32_t*>(&a1);
        f.z = *reinterpret_cast<uint32_t*>(&a2);
        f.w = *reinterpret_cast<uint32_t*>(&a3);
        frag[e] = f;
    }
    __syncthreads();

    // main loop
    const int wid = tid >> 5, lane = tid & 31;
    const int nb0 = nt * 64 + wid * N8W;
    const int r_in8 = lane >> 2;
    const uint32_t c4 = (uint32_t)(lane & 3) * 4;
    const int row0 = nb0 * 8 + r_in8;

    // qweight as uint4: row stride 256; ksplit offset = 512k = 16 uint4
    const uint4* qp = reinterpret_cast<const uint4*>(qw) + (size_t)row0 * 256 + ks * 16;

    float4 acc[N8W];
#pragma unroll
    for (int i = 0; i < N8W; i++) acc[i] = make_float4(0.f, 0.f, 0.f, 0.f);

#pragma unroll 1
    for (int g = 0; g < NGRP; g++) {
        __half2 s2[N8W], z2[N8W];
        const float* sp = scales + (size_t)(ks * NGRP + g) * NDIM + row0;
        const float* zp = zeros + (size_t)(ks * NGRP + g) * NDIM + row0;
#pragma unroll
        for (int i = 0; i < N8W; i++) {
            s2[i] = __half2half2(__float2half_rn(sp[i * 8]));
            z2[i] = __half2half2(__float2half_rn(zp[i * 8]));
        }
#pragma unroll
        for (int p = 0; p < 4; p++) {       // 4 uint4 = 8 k16-blocks per group-row
            uint4 wq[N8W];
#pragma unroll
            for (int i = 0; i < N8W; i++)
                wq[i] = qp[(size_t)i * 2048 + g * 4 + p];
#pragma unroll
            for (int sub = 0; sub < 2; sub++) {
                uint4 ah = frag[((g * 8 + p * 2 + sub) << 5) + lane];
#pragma unroll
                for (int i = 0; i < N8W; i++) {
                    uint32_t w0 = sub ? wq[i].z : wq[i].x;
                    uint32_t w1 = sub ? wq[i].w : wq[i].y;
                    uint32_t b0 = dq2(w0, c4, s2[i], z2[i]);
                    uint32_t b1 = dq2(w1, c4, s2[i], z2[i]);
                    mma16816(acc[i], ah.x, ah.y, ah.z, ah.w, b0, b1);
                }
            }
        }
    }

    // store partials
    const int off = r_in8 * 8 + (lane & 3) * 2;
#pragma unroll
    for (int i = 0; i < N8W; i++) {
        float* pb = &g_partial[ks][nb0 + i][0];
        *reinterpret_cast<float2*>(pb + off) = make_float2(acc[i].x, acc[i].y);
        *reinterpret_cast<float2*>(pb + 64 + off) = make_float2(acc[i].z, acc[i].w);
    }

    // signal tile arrival (tail CTA does the reduction)
    __threadfence();
    __syncthreads();
    if (tid == 0) atomicAdd(&g_cnt[nt], 1);
}

extern "C" void kernel_launch(void* const* d_in, const int* in_sizes, int n_in,
                              void* d_out, int out_size) {
    const float* x = (const float*)d_in[0];
    const int* qw = (const int*)d_in[1];
    const float* sc = (const float*)d_in[2];
    const float* zz = (const float*)d_in[3];
    const float* bias = (const float*)d_in[4];
    (void)in_sizes; (void)n_in; (void)out_size;

    cudaFuncSetAttribute(wq_gemm, cudaFuncAttributeMaxDynamicSharedMemorySize, SM_TOTAL);
    wq_gemm<<<TOTAL_CTAS, THREADS, SM_TOTAL>>>(x, qw, sc, zz, bias, (float*)d_out);
}